// round 15
// baseline (speedup 1.0000x reference)
#include <cuda_runtime.h>
#include <cuda_fp16.h>
#include <cstdint>

// Attention forward: out = softmax(Q K^T / 0.32) V
// B=4, H=16, S=2048, D=128, fp32 in/out.
//
// QK: S = q1k1 (fp16 mma, k16)  +  2^-11 * [ (2^11 q2)k1 + q1(2^11 k2) ] (fp8 e4m3
//     mma, k32 -> half the instruction count of fp16 correction passes).
// PV: O = p~ v~ (fp16; l summed from fp16-rounded p~ so rounding cancels in o/l).
// Pre-pass splits K/V once into __device__ globals (fp16 hi + scaled-fp8 parts).
// K/V cp.async'd directly into double-buffered ldsm-layout smem.

#define BM   128
#define BN   64
#define DH   128
#define SEQ  2048
#define NT   (SEQ/BN)
#define NTHREADS 256
#define QS   136        // fp16 elems per Q/K/V row (272 B)
#define KS   136
#define PS   72         // fp16 elems per P row (144 B)
#define R8   144        // bytes per fp8 row (128 data + 16 pad)

// ---- smem byte offsets ----
#define SQ1_B   0                    // q1 fp16   [128][272B]  34816
#define SQA_B   34816                // qa fp8    [128][144B]  18432
#define SQB_B   53248                // qb fp8    [128][144B]  18432
#define BUF0_B  71680                // buffer 0               53248
#define BUF_SZ  53248
#define K1A     17408                //   k1 fp16 [64][272B] at +0
#define K2A     26624                //   ka fp8  [64][144B] at +17408 (K1A)
#define VOF     35840                //   kb fp8  [64][144B] at +26624 (K2A)
                                     //   v  fp16 [64][272B] at +35840 (VOF)
#define SP_B    178176               // p fp16    [128][144B]  18432
#define SMEM_BYTES 196608

#define KVELEMS (64LL*2048*128)
__device__ __half  g_k1h[KVELEMS];
__device__ uint8_t g_ka[KVELEMS];    // e4m3(K)
__device__ uint8_t g_kb[KVELEMS];    // e4m3(2^11 * (K - fp16(K)))
__device__ __half  g_vh[KVELEMS];

__device__ __forceinline__ float ex2f(float x) {
    float y; asm("ex2.approx.ftz.f32 %0, %1;" : "=f"(y) : "f"(x)); return y;
}
__device__ __forceinline__ void mma_f16(float c[4],
                                        uint32_t a0, uint32_t a1, uint32_t a2, uint32_t a3,
                                        uint32_t b0, uint32_t b1) {
    asm volatile(
        "mma.sync.aligned.m16n8k16.row.col.f32.f16.f16.f32 "
        "{%0,%1,%2,%3}, {%4,%5,%6,%7}, {%8,%9}, {%0,%1,%2,%3};\n"
        : "+f"(c[0]), "+f"(c[1]), "+f"(c[2]), "+f"(c[3])
        : "r"(a0), "r"(a1), "r"(a2), "r"(a3), "r"(b0), "r"(b1));
}
__device__ __forceinline__ void mma_f8(float c[4],
                                       uint32_t a0, uint32_t a1, uint32_t a2, uint32_t a3,
                                       uint32_t b0, uint32_t b1) {
    asm volatile(
        "mma.sync.aligned.m16n8k32.row.col.f32.e4m3.e4m3.f32 "
        "{%0,%1,%2,%3}, {%4,%5,%6,%7}, {%8,%9}, {%0,%1,%2,%3};\n"
        : "+f"(c[0]), "+f"(c[1]), "+f"(c[2]), "+f"(c[3])
        : "r"(a0), "r"(a1), "r"(a2), "r"(a3), "r"(b0), "r"(b1));
}
__device__ __forceinline__ void ldsm_x4(uint32_t& r0, uint32_t& r1,
                                        uint32_t& r2, uint32_t& r3, uint32_t saddr) {
    asm volatile("ldmatrix.sync.aligned.m8n8.x4.shared.b16 {%0,%1,%2,%3}, [%4];"
                 : "=r"(r0), "=r"(r1), "=r"(r2), "=r"(r3) : "r"(saddr));
}
__device__ __forceinline__ void ldsm_x4_t(uint32_t& r0, uint32_t& r1,
                                          uint32_t& r2, uint32_t& r3, uint32_t saddr) {
    asm volatile("ldmatrix.sync.aligned.m8n8.x4.trans.shared.b16 {%0,%1,%2,%3}, [%4];"
                 : "=r"(r0), "=r"(r1), "=r"(r2), "=r"(r3) : "r"(saddr));
}
__device__ __forceinline__ void cp_async16(uint32_t dst_sa, const void* src) {
    asm volatile("cp.async.cg.shared.global [%0], [%1], 16;\n" :: "r"(dst_sa), "l"(src));
}
// pack 4 floats into 4 e4m3 bytes (element order = byte order)
__device__ __forceinline__ uint32_t pack_e4m3_4(float a, float b, float c, float d) {
    uint16_t lo16, hi16;
    asm("cvt.rn.satfinite.e4m3x2.f32 %0, %1, %2;" : "=h"(lo16) : "f"(b), "f"(a));
    asm("cvt.rn.satfinite.e4m3x2.f32 %0, %1, %2;" : "=h"(hi16) : "f"(d), "f"(c));
    return (uint32_t)lo16 | ((uint32_t)hi16 << 16);
}

// ---- pre-pass: K -> k1(fp16), ka(e4m3), kb(e4m3 of 2^11*residual); V -> fp16 ----
__global__ void __launch_bounds__(256) split_kv_kernel(const float* __restrict__ K,
                                                       const float* __restrict__ V) {
    const size_t i = (size_t)blockIdx.x * 256 + threadIdx.x;   // float4 index
    float4 k4 = reinterpret_cast<const float4*>(K)[i];
    __half h0 = __float2half_rn(k4.x), h1 = __float2half_rn(k4.y);
    __half h2 = __float2half_rn(k4.z), h3 = __float2half_rn(k4.w);
    reinterpret_cast<__half2*>(g_k1h)[2*i]   = __halves2half2(h0, h1);
    reinterpret_cast<__half2*>(g_k1h)[2*i+1] = __halves2half2(h2, h3);
    reinterpret_cast<uint32_t*>(g_ka)[i] = pack_e4m3_4(k4.x, k4.y, k4.z, k4.w);
    reinterpret_cast<uint32_t*>(g_kb)[i] = pack_e4m3_4(
        (k4.x - __half2float(h0)) * 2048.0f, (k4.y - __half2float(h1)) * 2048.0f,
        (k4.z - __half2float(h2)) * 2048.0f, (k4.w - __half2float(h3)) * 2048.0f);
    float4 v4 = reinterpret_cast<const float4*>(V)[i];
    reinterpret_cast<__half2*>(g_vh)[2*i]   =
        __halves2half2(__float2half_rn(v4.x), __float2half_rn(v4.y));
    reinterpret_cast<__half2*>(g_vh)[2*i+1] =
        __halves2half2(__float2half_rn(v4.z), __float2half_rn(v4.w));
}

__device__ __forceinline__ void issue_kv(int tid, uint32_t buf_sa,
                                         const __half* k1, const uint8_t* ka,
                                         const uint8_t* kb, const __half* vh) {
    #pragma unroll
    for (int j = 0; j < 4; j++) {
        const int i = tid + j * NTHREADS;                 // 0..1023 (fp16 chunks)
        const uint32_t d16 = (uint32_t)((i >> 4) * 272 + (i & 15) * 16);
        cp_async16(buf_sa + d16,       k1 + (size_t)i * 8);
        cp_async16(buf_sa + VOF + d16, vh + (size_t)i * 8);
    }
    #pragma unroll
    for (int j = 0; j < 2; j++) {
        const int i = tid + j * NTHREADS;                 // 0..511 (fp8 chunks)
        const uint32_t d8 = (uint32_t)((i >> 3) * R8 + (i & 7) * 16);
        cp_async16(buf_sa + K1A + d8, ka + (size_t)i * 16);
        cp_async16(buf_sa + K2A + d8, kb + (size_t)i * 16);
    }
    asm volatile("cp.async.commit_group;\n");
}

__global__ void __launch_bounds__(NTHREADS, 1)
attn_fwd_kernel(const float* __restrict__ Q, float* __restrict__ O) {
    extern __shared__ char smem[];
    __half* sq1 = reinterpret_cast<__half*>(smem + SQ1_B);
    __half* sp  = reinterpret_cast<__half*>(smem + SP_B);

    const int tid  = threadIdx.x;
    const int wid  = tid >> 5;
    const int lane = tid & 31;
    const int g    = lane >> 2;
    const int t    = lane & 3;
    const int wr   = wid * 16;

    const int mtile = blockIdx.x;
    const int bh    = blockIdx.y;

    const float*   Qg  = Q + ((size_t)bh * SEQ + (size_t)mtile * BM) * DH;
    const __half*  K1g = g_k1h + (size_t)bh * SEQ * DH;
    const uint8_t* Kag = g_ka  + (size_t)bh * SEQ * DH;
    const uint8_t* Kbg = g_kb  + (size_t)bh * SEQ * DH;
    const __half*  Vg  = g_vh  + (size_t)bh * SEQ * DH;
    float*         Og  = O + ((size_t)bh * SEQ + (size_t)mtile * BM) * DH;

    const uint32_t sbase   = (uint32_t)__cvta_generic_to_shared(smem);
    const uint32_t buf_sa0 = sbase + BUF0_B;
    const uint32_t buf_sa1 = buf_sa0 + BUF_SZ;

    // ---- prologue: issue tiles 0 and 1 ----
    issue_kv(tid, buf_sa0, K1g, Kag, Kbg, Vg);
    issue_kv(tid, buf_sa1, K1g + (size_t)BN * DH, Kag + (size_t)BN * DH,
             Kbg + (size_t)BN * DH, Vg + (size_t)BN * DH);

    const float qscale = (1.0f / 0.32f) * 1.4426950408889634f;

    // ---- load Q: q1 fp16, qa = e4m3(2^11*(q-q1)), qb = e4m3(q1) ----
    #pragma unroll
    for (int i = tid; i < BM * DH / 4; i += NTHREADS) {
        const int row = i >> 5;
        const int c4  = i & 31;
        float4 v4 = reinterpret_cast<const float4*>(Qg)[i];
        const float f0 = v4.x * qscale, f1 = v4.y * qscale;
        const float f2 = v4.z * qscale, f3 = v4.w * qscale;
        const __half h0 = __float2half_rn(f0), h1 = __float2half_rn(f1);
        const __half h2 = __float2half_rn(f2), h3 = __float2half_rn(f3);
        const float g0 = __half2float(h0), g1 = __half2float(h1);
        const float g2 = __half2float(h2), g3 = __half2float(h3);
        __half2* d1 = reinterpret_cast<__half2*>(sq1 + row * QS + c4 * 4);
        d1[0] = __halves2half2(h0, h1);
        d1[1] = __halves2half2(h2, h3);
        *reinterpret_cast<uint32_t*>(smem + SQA_B + row * R8 + c4 * 4) =
            pack_e4m3_4((f0 - g0) * 2048.0f, (f1 - g1) * 2048.0f,
                        (f2 - g2) * 2048.0f, (f3 - g3) * 2048.0f);
        *reinterpret_cast<uint32_t*>(smem + SQB_B + row * R8 + c4 * 4) =
            pack_e4m3_4(g0, g1, g2, g3);
    }

    float m_lo = -1e30f, m_hi = -1e30f;
    float l_lo = 0.0f,   l_hi = 0.0f;
    float o[16][4];
    #pragma unroll
    for (int i = 0; i < 16; i++) { o[i][0]=0.f; o[i][1]=0.f; o[i][2]=0.f; o[i][3]=0.f; }

    // ---- ldmatrix lane bases ----
    const uint32_t a_row = (uint32_t)(wr + (lane & 7) + ((lane >> 3) & 1) * 8);
    const uint32_t a_c8  = (uint32_t)((lane >> 4) * 8);
    const uint32_t sq1_ld = sbase + SQ1_B + (a_row * QS + a_c8) * 2u;
    const uint32_t sqa_ld = sbase + SQA_B + a_row * R8 + a_c8 * 2u;   // bytes: (lane>>4)*16
    const uint32_t sqb_ld = sbase + SQB_B + a_row * R8 + a_c8 * 2u;
    const uint32_t b_row = (uint32_t)((lane & 7) + ((lane >> 4) << 3));
    const uint32_t b_c8  = (uint32_t)(((lane >> 3) & 1) * 8);
    const uint32_t sk1_ld = buf_sa0 + (b_row * KS + b_c8) * 2u;
    const uint32_t ka_ld  = buf_sa0 + K1A + b_row * R8 + b_c8 * 2u;
    const uint32_t kb_ld  = buf_sa0 + K2A + b_row * R8 + b_c8 * 2u;
    const int mi = lane >> 3, mj = lane & 7;
    const uint32_t sv_lane_elem = (uint32_t)(((mi & 1) * 8 + mj) * KS + (mi >> 1) * 8);
    const uint32_t sv1_base = buf_sa0 + VOF + sv_lane_elem * 2u;
    const uint32_t sp_ld = sbase + SP_B + (a_row * PS + a_c8) * 2u;

    for (int kt = 0; kt < NT; kt++) {
        if (kt + 1 < NT) asm volatile("cp.async.wait_group 1;\n" ::: "memory");
        else             asm volatile("cp.async.wait_group 0;\n" ::: "memory");
        __syncthreads();
        const uint32_t bofs = (uint32_t)(kt & 1) * (uint32_t)BUF_SZ;

        // ---- main pass: s = q1 k1 (fp16, k16) ----
        float s[8][4];
        #pragma unroll
        for (int nt = 0; nt < 8; nt++) { s[nt][0]=0.f; s[nt][1]=0.f; s[nt][2]=0.f; s[nt][3]=0.f; }
        #pragma unroll
        for (int kc = 0; kc < 8; kc++) {
            uint32_t a1[4];
            ldsm_x4(a1[0], a1[1], a1[2], a1[3], sq1_ld + kc * 32u);
            #pragma unroll
            for (int pr = 0; pr < 4; pr++) {
                const uint32_t boff = (uint32_t)(pr * 16 * KS + kc * 16) * 2u + bofs;
                uint32_t b1[4];
                ldsm_x4(b1[0], b1[1], b1[2], b1[3], sk1_ld + boff);
                mma_f16(s[2*pr],   a1[0],a1[1],a1[2],a1[3], b1[0], b1[1]);
                mma_f16(s[2*pr+1], a1[0],a1[1],a1[2],a1[3], b1[2], b1[3]);
            }
        }
        // ---- correction pass: sc = (2^11 q2)ka + qb(2^11 k2) (fp8, k32) ----
        float sc[8][4];
        #pragma unroll
        for (int nt = 0; nt < 8; nt++) { sc[nt][0]=0.f; sc[nt][1]=0.f; sc[nt][2]=0.f; sc[nt][3]=0.f; }
        #pragma unroll
        for (int kc = 0; kc < 4; kc++) {   // 4 k32 chunks over DH=128
            uint32_t qa[4], qb[4];
            ldsm_x4(qa[0], qa[1], qa[2], qa[3], sqa_ld + kc * 32u);
            ldsm_x4(qb[0], qb[1], qb[2], qb[3], sqb_ld + kc * 32u);
            #pragma unroll
            for (int pr = 0; pr < 4; pr++) {
                const uint32_t boff = (uint32_t)(pr * 16 * R8 + kc * 32) + bofs;
                uint32_t ka[4], kb[4];
                ldsm_x4(ka[0], ka[1], ka[2], ka[3], ka_ld + boff);
                ldsm_x4(kb[0], kb[1], kb[2], kb[3], kb_ld + boff);
                mma_f8(sc[2*pr],   qa[0],qa[1],qa[2],qa[3], ka[0], ka[1]);
                mma_f8(sc[2*pr+1], qa[0],qa[1],qa[2],qa[3], ka[2], ka[3]);
                mma_f8(sc[2*pr],   qb[0],qb[1],qb[2],qb[3], kb[0], kb[1]);
                mma_f8(sc[2*pr+1], qb[0],qb[1],qb[2],qb[3], kb[2], kb[3]);
            }
        }
        // ---- fold: s += 2^-11 * sc ----
        #pragma unroll
        for (int nt = 0; nt < 8; nt++) {
            s[nt][0] = fmaf(sc[nt][0], 4.8828125e-4f, s[nt][0]);
            s[nt][1] = fmaf(sc[nt][1], 4.8828125e-4f, s[nt][1]);
            s[nt][2] = fmaf(sc[nt][2], 4.8828125e-4f, s[nt][2]);
            s[nt][3] = fmaf(sc[nt][3], 4.8828125e-4f, s[nt][3]);
        }

        // ---- online softmax (base-2) ----
        float mx_lo = -1e30f, mx_hi = -1e30f;
        #pragma unroll
        for (int nt = 0; nt < 8; nt++) {
            mx_lo = fmaxf(mx_lo, fmaxf(s[nt][0], s[nt][1]));
            mx_hi = fmaxf(mx_hi, fmaxf(s[nt][2], s[nt][3]));
        }
        mx_lo = fmaxf(mx_lo, __shfl_xor_sync(0xffffffffu, mx_lo, 1));
        mx_lo = fmaxf(mx_lo, __shfl_xor_sync(0xffffffffu, mx_lo, 2));
        mx_hi = fmaxf(mx_hi, __shfl_xor_sync(0xffffffffu, mx_hi, 1));
        mx_hi = fmaxf(mx_hi, __shfl_xor_sync(0xffffffffu, mx_hi, 2));

        const float mnew_lo = fmaxf(m_lo, mx_lo);
        const float mnew_hi = fmaxf(m_hi, mx_hi);
        const float corr_lo = ex2f(m_lo - mnew_lo);
        const float corr_hi = ex2f(m_hi - mnew_hi);
        m_lo = mnew_lo;
        m_hi = mnew_hi;

        float sum_lo = 0.f, sum_hi = 0.f;
        #pragma unroll
        for (int nt = 0; nt < 8; nt++) {
            const __half h0 = __float2half_rn(ex2f(s[nt][0] - m_lo));
            const __half h1 = __float2half_rn(ex2f(s[nt][1] - m_lo));
            const __half h2 = __float2half_rn(ex2f(s[nt][2] - m_hi));
            const __half h3 = __float2half_rn(ex2f(s[nt][3] - m_hi));
            sum_lo += __half2float(h0) + __half2float(h1);
            sum_hi += __half2float(h2) + __half2float(h3);
            *reinterpret_cast<__half2*>(sp + (wr + g)     * PS + nt * 8 + 2 * t) =
                __halves2half2(h0, h1);
            *reinterpret_cast<__half2*>(sp + (wr + g + 8) * PS + nt * 8 + 2 * t) =
                __halves2half2(h2, h3);
        }
        sum_lo += __shfl_xor_sync(0xffffffffu, sum_lo, 1);
        sum_lo += __shfl_xor_sync(0xffffffffu, sum_lo, 2);
        sum_hi += __shfl_xor_sync(0xffffffffu, sum_hi, 1);
        sum_hi += __shfl_xor_sync(0xffffffffu, sum_hi, 2);

        l_lo = l_lo * corr_lo + sum_lo;
        l_hi = l_hi * corr_hi + sum_hi;

        #pragma unroll
        for (int nt = 0; nt < 16; nt++) {
            o[nt][0] *= corr_lo; o[nt][1] *= corr_lo;
            o[nt][2] *= corr_hi; o[nt][3] *= corr_hi;
        }
        __syncwarp();   // sp rows are warp-private

        // ---- O += P~ V~ ----
        #pragma unroll
        for (int kc = 0; kc < 4; kc++) {
            uint32_t p[4];
            ldsm_x4(p[0], p[1], p[2], p[3], sp_ld + kc * 32u);
            #pragma unroll
            for (int ntp = 0; ntp < 8; ntp++) {
                const uint32_t off = (uint32_t)(kc * 16 * KS + ntp * 16) * 2u + bofs;
                uint32_t v0, v1, v2, v3;
                ldsm_x4_t(v0, v1, v2, v3, sv1_base + off);
                mma_f16(o[2*ntp],   p[0], p[1], p[2], p[3], v0, v1);
                mma_f16(o[2*ntp+1], p[0], p[1], p[2], p[3], v2, v3);
            }
        }

        // ---- refill finished buffer with tile kt+2 ----
        if (kt + 2 < NT) {
            __syncthreads();
            const size_t e = (size_t)(kt + 2) * BN * DH;
            issue_kv(tid, (kt & 1) ? buf_sa1 : buf_sa0,
                     K1g + e, Kag + e, Kbg + e, Vg + e);
        }
    }

    // ---- normalize and write out ----
    const float inv_lo = 1.0f / l_lo;
    const float inv_hi = 1.0f / l_hi;
    #pragma unroll
    for (int nt = 0; nt < 16; nt++) {
        const int c = nt * 8 + 2 * t;
        *reinterpret_cast<float2*>(Og + (wr + g)     * DH + c) =
            make_float2(o[nt][0] * inv_lo, o[nt][1] * inv_lo);
        *reinterpret_cast<float2*>(Og + (wr + g + 8) * DH + c) =
            make_float2(o[nt][2] * inv_hi, o[nt][3] * inv_hi);
    }
}

extern "C" void kernel_launch(void* const* d_in, const int* in_sizes, int n_in,
                              void* d_out, int out_size) {
    const float* q = (const float*)d_in[0];
    const float* k = (const float*)d_in[1];
    const float* v = (const float*)d_in[2];
    float* out = (float*)d_out;

    cudaFuncSetAttribute(attn_fwd_kernel,
                         cudaFuncAttributeMaxDynamicSharedMemorySize, SMEM_BYTES);

    split_kv_kernel<<<(int)(KVELEMS / 4 / 256), 256>>>(k, v);
    dim3 grid(SEQ / BM, 64);
    attn_fwd_kernel<<<grid, NTHREADS, SMEM_BYTES>>>(q, out);
}